// round 17
// baseline (speedup 1.0000x reference)
#include <cuda_runtime.h>
#include <math.h>

#define HH 112
#define WW 112
#define NPIX (HH*WW)          // 12544
#define GRID 7
#define NCELL 49
#define NFEAT 1822
#define BMAX 1024
#define TWO_PI_F 6.283185307179586f

// ---- scratch (static device arrays; no cudaMalloc anywhere) ----
__device__ float d_part[(size_t)BMAX * NCELL * 9];
__device__ unsigned int d_cnt[BMAX];     // zero-init; reset by last block

// ---- f32x2 packed helpers (sm_100+) ----
__device__ __forceinline__ unsigned long long pk2(float a, float b) {
    unsigned long long r;
    asm("mov.b64 %0, {%1, %2};" : "=l"(r) : "f"(a), "f"(b));
    return r;
}
__device__ __forceinline__ unsigned long long fma2(unsigned long long a,
                                                   unsigned long long b,
                                                   unsigned long long c) {
    unsigned long long d;
    asm("fma.rn.f32x2 %0, %1, %2, %3;" : "=l"(d) : "l"(a), "l"(b), "l"(c));
    return d;
}
__device__ __forceinline__ void upk2(unsigned long long v, float& lo, float& hi) {
    asm("mov.b64 {%0, %1}, %2;" : "=f"(lo), "=f"(hi) : "l"(v));
}
__device__ __forceinline__ unsigned int redux_add_u32(unsigned int v) {
    unsigned int r;
    asm("redux.sync.add.u32 %0, %1, 0xffffffff;" : "=r"(r) : "r"(v));
    return r;
}

// smem union: gabor role needs t2 (132*17 u64 = 17952 B) + sgs (112*37 f =
// 16576 B) = 34528 B; cell role needs tile (7*18*19 f) + stot (7*16 f) + flag.
#define SMEM_BYTES (17952 + 16608)

// =====================================================================
// Mega kernel: grid (14, B), 224 threads, 6 blocks/SM.
//   blockIdx.x in [0,7)  -> cell role  (cy = blockIdx.x); the 7th cell
//        block to finish an image also does the per-image finalize
//        (threadfence-reduction pattern, deterministic sum order).
//   blockIdx.x in [7,14) -> gabor role (cx = blockIdx.x - 7)
// Gabor taps are exactly even (tap[d] == tap[20-d]) -> 11 packed taps.
// =====================================================================
__global__ void __launch_bounds__(224, 6) mega(const float* __restrict__ img,
                                               const float* __restrict__ gk0,
                                               const float* __restrict__ gk1,
                                               float* __restrict__ out)
{
    __shared__ __align__(16) char smraw[SMEM_BYTES];

    const int b    = blockIdx.y;
    const int tid  = threadIdx.x;
    const int lane = tid & 31;
    const float* base = img + (size_t)b * 3 * NPIX;
    float* ob = out + (size_t)b * NFEAT;

    if (blockIdx.x < 7) {
        // =============================================================
        // CELL ROLE: warp-per-cell, 7 warps = 7 cell cols of row cy
        // =============================================================
        float (*tile)[18][19] = reinterpret_cast<float (*)[18][19]>(smraw);
        float (*stot)[16] = reinterpret_cast<float (*)[16]>(smraw + 7 * 18 * 19 * 4);
        int* slast = reinterpret_cast<int*>(smraw + 7 * 18 * 19 * 4 + 7 * 16 * 4);

        const int cy   = blockIdx.x;
        const int cx   = tid >> 5;
        const int cell = cy * GRID + cx;

        const int oy = cy * 16 - 1;
        const int ox = cx * 16 - 1;
        const int cg  = lane & 3;
        const int rp  = lane >> 2;
        const int gx0 = cx * 16 + cg * 4;
        const int r0  = rp * 2;
        const int gy0 = cy * 16 + r0;

        float (*tw)[19] = tile[cx];

        float acc[15];
        #pragma unroll
        for (int k = 0; k < 15; k++) acc[k] = 0.0f;
        unsigned int hR = 0, hG = 0, hB = 0;

        #pragma unroll
        for (int q = 0; q < 2; q++) {
            const int p = (gy0 + q) * WW + gx0;
            float4 r4 = *reinterpret_cast<const float4*>(base + p);
            float4 g4 = *reinterpret_cast<const float4*>(base + NPIX + p);
            float4 b4 = *reinterpret_cast<const float4*>(base + 2 * NPIX + p);
            float R[4]  = {r4.x, r4.y, r4.z, r4.w};
            float Gc[4] = {g4.x, g4.y, g4.z, g4.w};
            float Bl[4] = {b4.x, b4.y, b4.z, b4.w};

            #pragma unroll
            for (int j = 0; j < 4; j++)
                tw[r0 + 1 + q][cg * 4 + 1 + j] =
                    0.299f * R[j] + 0.587f * Gc[j] + 0.114f * Bl[j];

            #pragma unroll
            for (int j = 0; j < 4; j++) {
                const float rr = R[j], gg = Gc[j], bb = Bl[j];
                int ir = __float2int_rd(rr * 8.0f); if ((unsigned)ir < 8u) hR += 1u << (ir << 2);
                int ig = __float2int_rd(gg * 8.0f); if ((unsigned)ig < 8u) hG += 1u << (ig << 2);
                int ib = __float2int_rd(bb * 8.0f); if ((unsigned)ib < 8u) hB += 1u << (ib << 2);

                float maxc = fmaxf(rr, fmaxf(gg, bb));
                float minc = fminf(rr, fminf(gg, bb));
                float vv = maxc;
                float delta = maxc - minc;
                float dsafe = (delta == 0.0f) ? 1.0f : delta;
                float me = maxc + 1e-8f;
                float inv = __fdividef(1.0f, me * dsafe);
                float ss = delta * dsafe * inv;
                float invd = me * inv;
                float rc = (maxc - rr) * invd;
                float gc = (maxc - gg) * invd;
                float bc = (maxc - bb) * invd;
                float hh;
                if (maxc == rr)      hh = bc - gc;
                else if (maxc == gg) hh = 2.0f + rc - bc;
                else                 hh = 4.0f + gc - rc;
                hh = hh * (1.0f / 6.0f);
                hh = hh - floorf(hh);
                hh = hh * TWO_PI_F;

                acc[0] += rr; acc[1] += gg; acc[2] += bb;
                acc[3] += hh; acc[4] += ss; acc[5] += vv;
                acc[6] += hh * hh; acc[7] += ss * ss; acc[8] += vv * vv;
            }
        }

        // halo: 68 perimeter positions (clamp == edge pad)
        for (int i = lane; i < 68; i += 32) {
            int rr, cc;
            if (i < 18)      { rr = 0;          cc = i; }
            else if (i < 36) { rr = 17;         cc = i - 18; }
            else if (i < 52) { rr = i - 36 + 1; cc = 0; }
            else             { rr = i - 52 + 1; cc = 17; }
            int yy = min(max(oy + rr, 0), HH - 1);
            int xx = min(max(ox + cc, 0), WW - 1);
            int pp = yy * WW + xx;
            tw[rr][cc] = 0.299f * base[pp] + 0.587f * base[NPIX + pp] + 0.114f * base[2 * NPIX + pp];
        }
        __syncwarp();

        // Sobel (clamp via halo) + Laplacian (reflect)
        {
            float w[4][6];
            #pragma unroll
            for (int i = 0; i < 4; i++)
                #pragma unroll
                for (int c = 0; c < 6; c++)
                    w[i][c] = tw[r0 + i][cg * 4 + c];

            const bool eL = (gx0 == 0), eR = (gx0 == WW - 4);
            #pragma unroll
            for (int k = 0; k < 2; k++) {
                const int gy = gy0 + k;
                const bool eT = (gy == 0), eB = (gy == HH - 1);
                float colS[6], dd[6], lapTB[6];
                #pragma unroll
                for (int c = 0; c < 6; c++) {
                    colS[c]  = w[k][c] + 2.0f * w[k+1][c] + w[k+2][c];
                    dd[c]    = w[k+2][c] - w[k][c];
                    lapTB[c] = (eT ? w[k+2][c] : w[k][c]) + (eB ? w[k][c] : w[k+2][c]);
                }
                #pragma unroll
                for (int j = 0; j < 4; j++) {
                    float gxv = 0.125f * (colS[j + 2] - colS[j]);
                    float gyv = 0.125f * (dd[j] + 2.0f * dd[j + 1] + dd[j + 2]);
                    float d2  = gxv * gxv + gyv * gyv;
                    float mag = sqrtf(d2 + 1e-8f);
                    float ca  = (d2 > 0.0f) ? gxv * rsqrtf(d2) : 1.0f;

                    float vL  = (eL && j == 0) ? lapTB[j + 2] : lapTB[j];
                    float w1L = (eL && j == 0) ? w[k+1][j + 2] : w[k+1][j];
                    float vR  = (eR && j == 3) ? lapTB[j] : lapTB[j + 2];
                    float w1R = (eR && j == 3) ? w[k+1][j] : w[k+1][j + 2];
                    float nb  = vL + lapTB[j + 1] + vR + w1L + w1R;
                    float lap = nb * 0.0625f - 0.5f * w[k+1][j + 1];

                    acc[9]  += mag; acc[10] += mag * mag; acc[11] += ca;
                    acc[12] += lap; acc[13] += lap * lap; acc[14] += fabsf(lap);
                }
            }
        }

        // histogram: nibble -> 16-bit fields -> redux
        unsigned int h16[12];
        h16[0] = (hR & 0xFu)         | ((hR << 12) & 0xF0000u);
        h16[1] = ((hR >> 8)  & 0xFu) | ((hR << 4)  & 0xF0000u);
        h16[2] = ((hR >> 16) & 0xFu) | ((hR >> 4)  & 0xF0000u);
        h16[3] = ((hR >> 24) & 0xFu) | ((hR >> 12) & 0xF0000u);
        h16[4] = (hG & 0xFu)         | ((hG << 12) & 0xF0000u);
        h16[5] = ((hG >> 8)  & 0xFu) | ((hG << 4)  & 0xF0000u);
        h16[6] = ((hG >> 16) & 0xFu) | ((hG >> 4)  & 0xF0000u);
        h16[7] = ((hG >> 24) & 0xFu) | ((hG >> 12) & 0xF0000u);
        h16[8] = (hB & 0xFu)         | ((hB << 12) & 0xF0000u);
        h16[9] = ((hB >> 8)  & 0xFu) | ((hB << 4)  & 0xF0000u);
        h16[10]= ((hB >> 16) & 0xFu) | ((hB >> 4)  & 0xF0000u);
        h16[11]= ((hB >> 24) & 0xFu) | ((hB >> 12) & 0xF0000u);
        #pragma unroll
        for (int k = 0; k < 12; k++) h16[k] = redux_add_u32(h16[k]);

        if (lane < 24) {
            unsigned int pick = 0;
            #pragma unroll
            for (int j = 0; j < 12; j++)
                if ((lane >> 1) == j) pick = h16[j];
            unsigned int cnt = (pick >> (16 * (lane & 1))) & 0xFFFFu;
            ob[3 + ((size_t)cell * 3 + (lane >> 3)) * 8 + (lane & 7)] = (float)cnt * (1.0f / 256.0f);
        }

        #pragma unroll
        for (int k = 0; k < 15; k++) {
            float x = acc[k];
            #pragma unroll
            for (int o = 16; o > 0; o >>= 1) x += __shfl_down_sync(0xffffffffu, x, o);
            if (lane == 0) stot[cx][k] = x;
        }
        __syncwarp();

        if (lane < 9) d_part[((size_t)b * NCELL + cell) * 9 + lane] = stot[cx][lane];
        if (lane >= 9 && lane < 12) ob[1185 + cell * 3 + (lane - 9)] = stot[cx][lane - 6] * (1.0f / 256.0f);
        if (lane == 12) {
            float sm = stot[cx][9], sq = stot[cx][10];
            ob[1332 + cell * 4 + 0] = sm * (1.0f / 256.0f);
            ob[1332 + cell * 4 + 1] = sqrtf(fmaxf(0.0f, (sq - sm * sm * (1.0f / 256.0f)) * (1.0f / 255.0f)));
            ob[1332 + cell * 4 + 2] = sq * (1.0f / 256.0f);
            ob[1332 + cell * 4 + 3] = stot[cx][11] * (1.0f / 256.0f);
        }
        if (lane == 13) {
            float lm = stot[cx][12], lq = stot[cx][13];
            ob[1528 + cell * 4 + 0] = lm * (1.0f / 256.0f);
            ob[1528 + cell * 4 + 1] = sqrtf(fmaxf(0.0f, (lq - lm * lm * (1.0f / 256.0f)) * (1.0f / 255.0f)));
            ob[1528 + cell * 4 + 2] = lq * (1.0f / 256.0f);
            ob[1528 + cell * 4 + 3] = stot[cx][14] * (1.0f / 256.0f);
        }

        // ---- per-image finalize by the last-arriving cell block ----
        __threadfence();
        __syncthreads();
        if (tid == 0) {
            unsigned int prev = atomicAdd(&d_cnt[b], 1u);
            *slast = (prev == 6u) ? 1 : 0;
        }
        __syncthreads();
        if (*slast) {
            if (tid < 9) {
                const float* pp = d_part + (size_t)b * NCELL * 9;
                float s = 0.0f;
                #pragma unroll 7
                for (int c = 0; c < NCELL; c++) s += pp[c * 9 + tid];
                const float N = (float)NPIX;
                float partner = __shfl_down_sync(0x1FFu, s, 3);
                if (tid < 3) {
                    ob[tid] = s / N;
                } else if (tid < 6) {
                    int k = tid - 3;
                    float var = (partner - s * s / N) / (N - 1.0f);
                    ob[1179 + 2 * k] = s / N;
                    ob[1180 + 2 * k] = sqrtf(fmaxf(var, 0.0f));
                }
            }
            if (tid == 0) d_cnt[b] = 0u;   // reset for next graph replay
        }
    } else {
        // =============================================================
        // GABOR ROLE: strip-fused separable passes; symmetric taps
        // (tap[d] == tap[20-d]) -> 11 packed taps per phase.
        // =============================================================
        unsigned long long* t2 = reinterpret_cast<unsigned long long*>(smraw);          // 132*17 u64
        float* sgs = reinterpret_cast<float*>(smraw + 132 * 17 * 8);                    // 112*37 f

        const int cx = blockIdx.x - 7;
        const int x0 = cx * 16;

        unsigned long long tapH[11];
        #pragma unroll
        for (int d = 0; d < 11; d++)
            tapH[d] = pk2(__ldg(&gk0[210 + d]), __ldg(&gk1[210 + d]));

        // zero t2 halo rows (0..9, 122..131)
        for (int i = tid; i < 20 * 16; i += 224) {
            int rr = i >> 4, cc = i & 15;
            int row = (rr < 10) ? rr : rr + 112;
            t2[row * 17 + cc] = 0ULL;
        }
        // gray strip from RGB: cols x0-10 .. x0+25, zero outside image
        for (int i = tid; i < 112 * 36; i += 224) {
            int row = i / 36, lc = i % 36;
            int gx = x0 - 10 + lc;
            float v = 0.0f;
            if (gx >= 0 && gx < WW) {
                int p = row * WW + gx;
                v = 0.299f * base[p] + 0.587f * base[NPIX + p] + 0.114f * base[2 * NPIX + p];
            }
            sgs[row * 37 + lc] = v;
        }
        __syncthreads();

        // h-pass: thread = (row, half); 8 outputs each
        {
            const int row  = (tid < 112) ? tid : tid - 112;
            const int j0   = (tid < 112) ? 0 : 8;
            const float* bp = sgs + row * 37 + j0;
            unsigned long long a[8];
            #pragma unroll
            for (int i = 0; i < 8; i++) a[i] = 0ULL;
            #pragma unroll
            for (int k = 0; k < 28; k++) {
                float v = bp[k];
                unsigned long long vp = pk2(v, v);
                #pragma unroll
                for (int i = 0; i < 8; i++) {
                    int d = k - i;
                    if (d >= 0 && d < 21) {
                        int ds = (d < 11) ? d : 20 - d;   // symmetric tap remap
                        a[i] = fma2(tapH[ds], vp, a[i]);
                    }
                }
            }
            unsigned long long* o = t2 + (row + 10) * 17 + j0;
            #pragma unroll
            for (int i = 0; i < 8; i++) o[i] = a[i];
        }

        unsigned long long tapV[11];
        {
            float inv0 = __fdividef(1.0f, __ldg(&gk0[220]));
            float inv1 = __fdividef(1.0f, __ldg(&gk1[220]));
            #pragma unroll
            for (int d = 0; d < 11; d++)
                tapV[d] = pk2(__ldg(&gk0[d * 21 + 10]) * inv0,
                              __ldg(&gk1[d * 21 + 10]) * inv1);
        }
        __syncthreads();

        // v-pass: 16 cols x 14 y-groups of 8; warp w == cell row w
        const int x = tid & 15, ty = tid >> 4, yb = ty * 8;
        unsigned long long a[8];
        #pragma unroll
        for (int j = 0; j < 8; j++) a[j] = 0ULL;
        #pragma unroll
        for (int k = 0; k < 28; k++) {
            unsigned long long vp = t2[(yb + k) * 17 + x];
            #pragma unroll
            for (int j = 0; j < 8; j++) {
                int d = k - j;
                if (d >= 0 && d < 21) {
                    int ds = (d < 11) ? d : 20 - d;       // symmetric tap remap
                    a[j] = fma2(tapV[ds], vp, a[j]);
                }
            }
        }
        float s0 = 0.0f, s1 = 0.0f;
        #pragma unroll
        for (int j = 0; j < 8; j++) {
            float lo, hi;
            upk2(a[j], lo, hi);
            s0 += fabsf(lo);
            s1 += fabsf(hi);
        }
        #pragma unroll
        for (int o = 16; o > 0; o >>= 1) {
            s0 += __shfl_down_sync(0xffffffffu, s0, o);
            s1 += __shfl_down_sync(0xffffffffu, s1, o);
        }
        if (lane == 0) {
            int w = tid >> 5;             // cell row
            ob[1724 + w * GRID + cx] = s0 * (1.0f / 256.0f);
            ob[1773 + w * GRID + cx] = s1 * (1.0f / 256.0f);
        }
    }
}

// =====================================================================
extern "C" void kernel_launch(void* const* d_in, const int* in_sizes, int n_in,
                              void* d_out, int out_size)
{
    const float* img = (const float*)d_in[0];
    const float* gk0 = (const float*)d_in[1];
    const float* gk1 = (const float*)d_in[2];
    float* out = (float*)d_out;

    int B = in_sizes[0] / (3 * NPIX);
    if (B > BMAX) B = BMAX;

    mega<<<dim3(14, B), 224>>>(img, gk0, gk1, out);
}